// round 7
// baseline (speedup 1.0000x reference)
#include <cuda_runtime.h>
#include <cuda_bf16.h>
#include <cuda_fp8.h>
#include <cstdint>

// Problem constants
#define VOCAB   50000
#define DDIM    128
#define CCH     128
#define NCLS    200
#define NSEQ    4096
#define SLEN    128
#define NVID    256
#define NSLOT   12

// fp8 scaling: x*256, w*64 -> product scale 16384
#define XSCALE  256.0f
#define WSCALE  64.0f
#define INVS    (1.0f / 16384.0f)

// Main kernel: one CTA = 64 tokens of one sequence (2 CTAs per sequence)
#define MROWS   64
#define XROWS   68                          // 64 + 4 lookahead rows
#define PITCH   144                         // fp8 bytes per row in smem
#define X_BYTES (XROWS * PITCH)             // 9792
#define B_BYTES (128 * PITCH)               // 18432
#define OFF_X    0
#define OFF_B    (X_BYTES)                  // 3 buffers
#define OFF_RED  (OFF_B + 3 * B_BYTES)      // 2*128 floats
#define OFF_IDS  (OFF_RED + 1024)           // 68 ints -> 272B
#define SMEM_TOTAL (OFF_IDS + 288 + 32)

// Scratch in device globals (no allocations allowed)
__device__ uint8_t g_e8[(size_t)VOCAB * DDIM];     // fp8 e4m3, x*256
__device__ uint8_t g_w8[NSLOT * DDIM * CCH];       // fp8 e4m3, w*64, [slot][c][d]
__device__ float   g_part[2 * NSEQ * 3 * CCH];     // partial channel maxes (raw scale)

// ---------------------------------------------------------------------------
// Conversion / init kernels
// ---------------------------------------------------------------------------
__global__ void cvt_emb8_kernel(const float* __restrict__ emb) {
    int64_t i = (int64_t)blockIdx.x * blockDim.x + threadIdx.x;
    int64_t n = (int64_t)VOCAB * DDIM;
    if (i < n)
        g_e8[i] = (uint8_t)__nv_cvt_float_to_fp8(emb[i] * XSCALE, __NV_SATFINITE, __NV_E4M3);
}

// W[slot][d][c] -> g_w8[slot][c][d]
__global__ void cvt_w8_kernel(const float* __restrict__ W3,
                              const float* __restrict__ W4,
                              const float* __restrict__ W5) {
    int i = blockIdx.x * blockDim.x + threadIdx.x;          // < 196608
    if (i >= NSLOT * DDIM * CCH) return;
    int slot = i >> 14;
    int r    = i & 16383;
    int c    = r >> 7;
    int d    = r & 127;
    float v;
    if (slot < 3)      v = W3[(slot)     * 16384 + d * CCH + c];
    else if (slot < 7) v = W4[(slot - 3) * 16384 + d * CCH + c];
    else               v = W5[(slot - 7) * 16384 + d * CCH + c];
    g_w8[slot * 16384 + c * 128 + d] =
        (uint8_t)__nv_cvt_float_to_fp8(v * WSCALE, __NV_SATFINITE, __NV_E4M3);
}

__global__ void zero_out_kernel(float* __restrict__ out) {
    int i = blockIdx.x * blockDim.x + threadIdx.x;
    if (i < NVID * NCLS) out[i] = 0.0f;   // scores > 0, so 0 acts as -inf
}

// ---------------------------------------------------------------------------
// MMA / async-copy helpers
// ---------------------------------------------------------------------------
__device__ __forceinline__ void ldsm_x4(uint32_t* r, uint32_t addr) {
    asm volatile("ldmatrix.sync.aligned.m8n8.x4.shared.b16 {%0,%1,%2,%3}, [%4];\n"
                 : "=r"(r[0]), "=r"(r[1]), "=r"(r[2]), "=r"(r[3]) : "r"(addr));
}
__device__ __forceinline__ void mma_fp8(float* c, const uint32_t* a, uint32_t b0, uint32_t b1) {
    asm volatile(
        "mma.sync.aligned.m16n8k32.row.col.f32.e4m3.e4m3.f32 "
        "{%0,%1,%2,%3}, {%4,%5,%6,%7}, {%8,%9}, {%0,%1,%2,%3};\n"
        : "+f"(c[0]), "+f"(c[1]), "+f"(c[2]), "+f"(c[3])
        : "r"(a[0]), "r"(a[1]), "r"(a[2]), "r"(a[3]), "r"(b0), "r"(b1));
}
__device__ __forceinline__ void cpasync16(uint32_t dst, const void* src) {
    asm volatile("cp.async.cg.shared.global [%0], [%1], 16;\n" :: "r"(dst), "l"(src));
}
__device__ __forceinline__ void cp_commit() {
    asm volatile("cp.async.commit_group;\n" ::: "memory");
}
template <int N>
__device__ __forceinline__ void cp_wait() {
    asm volatile("cp.async.wait_group %0;\n" :: "n"(N) : "memory");
}

// stage one weight slot [128 c][128 d bytes] into pitch-144 smem
__device__ __forceinline__ void stage_w(int slot, uint32_t bbase, int tid) {
    const uint8_t* src = g_w8 + slot * 16384;
    #pragma unroll
    for (int i = 0; i < 4; i++) {
        int idx = tid + i * 256;                 // 0..1023 16B chunks
        int row = idx >> 3, ch = idx & 7;
        cpasync16(bbase + row * PITCH + ch * 16, src + idx * 16);
    }
}

// ---------------------------------------------------------------------------
// Main conv kernel: grid 8192 (seq = bx>>1, half = bx&1), 8 warps,
// warp tile 32 (tokens) x 32 (channels) -> 32 acc regs, 3 CTAs/SM.
// ---------------------------------------------------------------------------
__global__ __launch_bounds__(256, 3)
void conv_kernel(const int* __restrict__ input_x) {
    extern __shared__ char smem[];
    float* red = (float*)(smem + OFF_RED);     // [2][128]
    int*   ids = (int*)(smem + OFF_IDS);       // [68]

    const int tid  = threadIdx.x;
    const int lane = tid & 31;
    const int warp = tid >> 5;
    const int wm   = warp >> 2;    // 0..1 : M tile of 32 rows
    const int wn   = warp & 3;     // 0..3 : N tile of 32 channels
    const int bx   = blockIdx.x;
    const int n    = bx >> 1;
    const int h    = bx & 1;       // token half

    const uint32_t sb = (uint32_t)__cvta_generic_to_shared(smem);
    const uint32_t xb = sb + OFF_X;

    // ---- token ids for rows h*64 .. h*64+67 (clamped) ----
    if (tid < XROWS) {
        int g = h * MROWS + tid;
        ids[tid] = (g < SLEN) ? input_x[n * SLEN + g] : -1;
    }
    __syncthreads();

    // ---- gather X rows (68 x 128B) : cp.async group 0 ----
    #pragma unroll
    for (int i = 0; i < 3; i++) {
        int idx = tid + i * 256;               // 0..543
        if (idx < XROWS * 8) {
            int t = idx >> 3, ch = idx & 7;
            int id = ids[t];
            if (id >= 0)
                cpasync16(xb + t * PITCH + ch * 16, g_e8 + (size_t)id * DDIM + ch * 16);
            else
                *(uint4*)(smem + OFF_X + t * PITCH + ch * 16) = make_uint4(0, 0, 0, 0);
        }
    }
    // ---- prefetch weight slots 0,1 ----
    cp_commit();                               // group: gather (+anything prior)
    stage_w(0, sb + OFF_B, tid);              cp_commit();
    stage_w(1, sb + OFF_B + B_BYTES, tid);    cp_commit();

    // per-warp invariant address pieces
    const uint32_t aBase = xb + (wm * 32 + (lane & 15)) * PITCH + ((lane >> 4) << 4);
    const uint32_t bRowOff = (uint32_t)((wn * 32 + (lane & 7) + ((lane >> 4) << 3)) * PITCH
                                        + (((lane >> 3) & 1) << 4));

    int slot = 0;
    #pragma unroll 1
    for (int conv = 0; conv < 3; conv++) {
        const int ksz = conv + 3;
        float acc[2][4][4];
        #pragma unroll
        for (int mf = 0; mf < 2; mf++)
            #pragma unroll
            for (int o = 0; o < 4; o++)
                #pragma unroll
                for (int q = 0; q < 4; q++) acc[mf][o][q] = 0.0f;

        #pragma unroll 1
        for (int j = 0; j < ksz; j++, slot++) {
            if (slot < NSLOT - 1) cp_wait<1>(); else cp_wait<0>();
            __syncthreads();                   // slot staged; slot-1 compute done everywhere
            if (slot + 2 < NSLOT) {            // restage buffer freed by slot-1
                stage_w(slot + 2, sb + OFF_B + ((slot + 2) % 3) * B_BYTES, tid);
                cp_commit();
            }
            const uint32_t bw = sb + OFF_B + (slot % 3) * B_BYTES + bRowOff;
            const uint32_t aj = aBase + (uint32_t)j * PITCH;

            #pragma unroll
            for (int dck = 0; dck < 4; dck++) {
                uint32_t a[2][4];
                ldsm_x4(a[0], aj + dck * 32);
                ldsm_x4(a[1], aj + 16 * PITCH + dck * 32);
                #pragma unroll
                for (int ng = 0; ng < 2; ng++) {
                    uint32_t b[4];
                    ldsm_x4(b, bw + ng * 16 * PITCH + dck * 32);
                    mma_fp8(acc[0][ng * 2 + 0], a[0], b[0], b[1]);
                    mma_fp8(acc[1][ng * 2 + 0], a[1], b[0], b[1]);
                    mma_fp8(acc[0][ng * 2 + 1], a[0], b[2], b[3]);
                    mma_fp8(acc[1][ng * 2 + 1], a[1], b[2], b[3]);
                }
            }
        }

        // ---- partial maxpool: valid window starts t_global <= SLEN - ksz ----
        const int tmax = SLEN - ksz;
        const float NEG = -1e30f;
        float lmax[4][2];
        #pragma unroll
        for (int o = 0; o < 4; o++) {
            float m0 = NEG, m1 = NEG;
            #pragma unroll
            for (int mf = 0; mf < 2; mf++) {
                int tg = h * MROWS + wm * 32 + mf * 16 + (lane >> 2);
                bool v0 = (tg <= tmax);
                bool v1 = (tg + 8 <= tmax);
                m0 = fmaxf(m0, v0 ? acc[mf][o][0] : NEG);
                m1 = fmaxf(m1, v0 ? acc[mf][o][1] : NEG);
                m0 = fmaxf(m0, v1 ? acc[mf][o][2] : NEG);
                m1 = fmaxf(m1, v1 ? acc[mf][o][3] : NEG);
            }
            lmax[o][0] = m0; lmax[o][1] = m1;
        }
        #pragma unroll
        for (int o = 0; o < 4; o++)
            #pragma unroll
            for (int p = 0; p < 2; p++) {
                float v = lmax[o][p];
                v = fmaxf(v, __shfl_xor_sync(0xffffffffu, v, 4));
                v = fmaxf(v, __shfl_xor_sync(0xffffffffu, v, 8));
                v = fmaxf(v, __shfl_xor_sync(0xffffffffu, v, 16));
                lmax[o][p] = v;
            }
        if ((lane >> 2) == 0) {
            #pragma unroll
            for (int o = 0; o < 4; o++)
                #pragma unroll
                for (int p = 0; p < 2; p++)
                    red[wm * 128 + wn * 32 + o * 8 + (lane & 3) * 2 + p] = lmax[o][p];
        }
        __syncthreads();
        if (tid < CCH)
            g_part[(size_t)bx * (3 * CCH) + conv * CCH + tid] =
                fmaxf(red[tid], red[128 + tid]);
        __syncthreads();                       // red free for next conv
    }
}

// ---------------------------------------------------------------------------
// Epilogue kernel: combine halves, bias, 384x200 GEMM, sigmoid, segment max.
// grid 128 blocks x 256 thr, 32 sequences per block.
// ---------------------------------------------------------------------------
#define EP_SEQ  32
#define FPITCH  385
__global__ __launch_bounds__(256)
void epilogue_kernel(const int* __restrict__ seg_ids,
                     const float* __restrict__ b3,
                     const float* __restrict__ b4,
                     const float* __restrict__ b5,
                     const float* __restrict__ Wout,
                     const float* __restrict__ bout,
                     float* __restrict__ out) {
    extern __shared__ float feat[];            // [EP_SEQ][FPITCH]
    const int tid  = threadIdx.x;
    const int seq0 = blockIdx.x * EP_SEQ;

    // stage features: max over halves, descale, +bias
    for (int i = tid; i < EP_SEQ * 384; i += 256) {
        int s = i / 384, k = i - s * 384;
        int conv = k >> 7, c = k & 127;
        const float* pp = g_part + (size_t)(2 * (seq0 + s)) * 384;
        float v = fmaxf(pp[k], pp[384 + k]);
        float bias = (conv == 0) ? b3[c] : ((conv == 1) ? b4[c] : b5[c]);
        feat[s * FPITCH + k] = v * INVS + bias;
    }
    __syncthreads();

    // GEMM: pair p -> class c = p>>5 (uniform per warp), seq s = p&31 (lane)
    for (int p = tid; p < EP_SEQ * NCLS; p += 256) {
        int c = p >> 5, s = p & 31;
        const float* f = feat + s * FPITCH;
        float a = bout[c];
        #pragma unroll 8
        for (int kk = 0; kk < 384; kk++)
            a = fmaf(f[kk], Wout[kk * NCLS + c], a);
        float sgm = 1.0f / (1.0f + expf(-a));
        int seg = seg_ids[seq0 + s];
        atomicMax((int*)&out[seg * NCLS + c], __float_as_int(sgm));  // sgm > 0
    }
}

// ---------------------------------------------------------------------------
// Launch
// ---------------------------------------------------------------------------
extern "C" void kernel_launch(void* const* d_in, const int* in_sizes, int n_in,
                              void* d_out, int out_size) {
    const int*   input_x = (const int*)d_in[0];
    const int*   seg_ids = (const int*)d_in[1];
    const float* emb     = (const float*)d_in[2];
    const float* W3      = (const float*)d_in[3];
    const float* b3      = (const float*)d_in[4];
    const float* W4      = (const float*)d_in[5];
    const float* b4      = (const float*)d_in[6];
    const float* W5      = (const float*)d_in[7];
    const float* b5      = (const float*)d_in[8];
    const float* Wout    = (const float*)d_in[9];
    const float* bout    = (const float*)d_in[10];
    float*       out     = (float*)d_out;

    cudaFuncSetAttribute(conv_kernel, cudaFuncAttributeMaxDynamicSharedMemorySize, SMEM_TOTAL);
    const int ep_smem = EP_SEQ * FPITCH * 4;
    cudaFuncSetAttribute(epilogue_kernel, cudaFuncAttributeMaxDynamicSharedMemorySize, ep_smem);

    {
        int64_t nemb = (int64_t)VOCAB * DDIM;
        cvt_emb8_kernel<<<(int)((nemb + 255) / 256), 256>>>(emb);
    }
    cvt_w8_kernel<<<(NSLOT * DDIM * CCH + 255) / 256, 256>>>(W3, W4, W5);
    zero_out_kernel<<<(NVID * NCLS + 255) / 256, 256>>>(out);

    conv_kernel<<<2 * NSEQ, 256, SMEM_TOTAL>>>(input_x);
    epilogue_kernel<<<NSEQ / EP_SEQ, 256, ep_smem>>>(seg_ids, b3, b4, b5, Wout, bout, out);
}